// round 1
// baseline (speedup 1.0000x reference)
#include <cuda_runtime.h>

#define N_NODES 50000
#define N_EDGES 800000
#define NODE_DIM 64
#define EDGE_DIM 32
#define HIDDEN 64

// Scratch (no cudaMalloc allowed): aggregation buffer + degree counts.
__device__ float g_agg[N_NODES * HIDDEN];
__device__ float g_deg[N_NODES];

// ---------------------------------------------------------------------------
// Kernel 0: zero the scratch buffers (graph-capturable, deterministic)
// ---------------------------------------------------------------------------
__global__ void zero_kernel() {
    int i = blockIdx.x * blockDim.x + threadIdx.x;
    int stride = gridDim.x * blockDim.x;
    for (int idx = i; idx < N_NODES * HIDDEN; idx += stride) g_agg[idx] = 0.0f;
    for (int idx = i; idx < N_NODES; idx += stride) g_deg[idx] = 0.0f;
}

// ---------------------------------------------------------------------------
// Kernel 1: per-edge message MLP + atomic scatter to g_agg.
// One warp computes 4 edges simultaneously; weights live in shared memory.
// Lane n holds hidden/output channels n and n+32.
//   x layout per edge (96 = 64 node + 32 edge):
//     x0 = node[src][lane], x1 = node[src][32+lane], x2 = edge[e][lane]
// ---------------------------------------------------------------------------
__global__ __launch_bounds__(256, 2)
void edge_kernel(const float* __restrict__ nf, const float* __restrict__ ef,
                 const float* __restrict__ w1, const float* __restrict__ b1,
                 const float* __restrict__ w2, const float* __restrict__ b2,
                 const int* __restrict__ src, const int* __restrict__ dst) {
    extern __shared__ float sh[];
    float* sW1 = sh;            // 2*96*64 = 12288
    float* sB1 = sh + 12288;    // 2*64   = 128
    float* sW2 = sh + 12416;    // 2*64*64= 8192
    float* sB2 = sh + 20608;    // 2*64   = 128  -> total 20736 floats

    for (int i = threadIdx.x; i < 12288; i += blockDim.x) sW1[i] = w1[i];
    for (int i = threadIdx.x; i < 8192;  i += blockDim.x) sW2[i] = w2[i];
    if (threadIdx.x < 128) sB1[threadIdx.x] = b1[threadIdx.x];
    else if (threadIdx.x < 256) sB2[threadIdx.x - 128] = b2[threadIdx.x - 128];
    __syncthreads();

    const int lane   = threadIdx.x & 31;
    const int warp   = (blockIdx.x * blockDim.x + threadIdx.x) >> 5;
    const int nwarps = (gridDim.x * blockDim.x) >> 5;

    for (int e0 = warp * 4; e0 < N_EDGES; e0 += nwarps * 4) {
        // ---- gather inputs (clamped for the remainder group) ----
        int   eidx[4];
        float x0[4], x1[4], x2[4];
        #pragma unroll
        for (int i = 0; i < 4; i++) {
            int e = e0 + i; if (e >= N_EDGES) e = N_EDGES - 1;
            eidx[i] = e;
            int s = src[e];
            x0[i] = nf[s * NODE_DIM + lane];
            x1[i] = nf[s * NODE_DIM + 32 + lane];
            x2[i] = ef[e * EDGE_DIM + lane];
        }

        // message accumulator, seeded with b2[0]+b2[1]
        float m0[4], m1[4];
        {
            float s0 = sB2[lane] + sB2[64 + lane];
            float s1 = sB2[32 + lane] + sB2[96 + lane];
            #pragma unroll
            for (int i = 0; i < 4; i++) { m0[i] = s0; m1[i] = s1; }
        }

        #pragma unroll
        for (int l = 0; l < 2; l++) {
            const float* W1 = sW1 + l * 6144;
            const float* W2 = sW2 + l * 4096;
            float h0[4], h1[4];
            {
                float bA = sB1[l * 64 + lane];
                float bB = sB1[l * 64 + 32 + lane];
                #pragma unroll
                for (int i = 0; i < 4; i++) { h0[i] = bA; h1[i] = bB; }
            }
            // h = x @ W1 : k runs over 96, split into 3 chunks of 32
            #pragma unroll
            for (int c = 0; c < 3; c++) {
                #pragma unroll 8
                for (int kk = 0; kk < 32; kk++) {
                    int k = c * 32 + kk;
                    float wA = W1[k * 64 + lane];
                    float wB = W1[k * 64 + 32 + lane];
                    #pragma unroll
                    for (int i = 0; i < 4; i++) {
                        float xi = (c == 0) ? x0[i] : ((c == 1) ? x1[i] : x2[i]);
                        float xk = __shfl_sync(0xFFFFFFFFu, xi, kk);
                        h0[i] = fmaf(xk, wA, h0[i]);
                        h1[i] = fmaf(xk, wB, h1[i]);
                    }
                }
            }
            #pragma unroll
            for (int i = 0; i < 4; i++) {
                h0[i] = fmaxf(h0[i], 0.0f);
                h1[i] = fmaxf(h1[i], 0.0f);
            }
            // m += h @ W2 : j runs over 64, 2 chunks of 32
            #pragma unroll
            for (int c = 0; c < 2; c++) {
                #pragma unroll 8
                for (int jj = 0; jj < 32; jj++) {
                    int j = c * 32 + jj;
                    float wA = W2[j * 64 + lane];
                    float wB = W2[j * 64 + 32 + lane];
                    #pragma unroll
                    for (int i = 0; i < 4; i++) {
                        float hi = (c == 0) ? h0[i] : h1[i];
                        float hj = __shfl_sync(0xFFFFFFFFu, hi, jj);
                        m0[i] = fmaf(hj, wA, m0[i]);
                        m1[i] = fmaf(hj, wB, m1[i]);
                    }
                }
            }
        }

        // ---- scatter to destination nodes ----
        #pragma unroll
        for (int i = 0; i < 4; i++) {
            if (e0 + i < N_EDGES) {
                int d = dst[eidx[i]];
                atomicAdd(&g_agg[d * HIDDEN + lane], m0[i]);
                atomicAdd(&g_agg[d * HIDDEN + 32 + lane], m1[i]);
                if (lane == 0) atomicAdd(&g_deg[d], 1.0f);
            }
        }
    }
}

// ---------------------------------------------------------------------------
// Kernel 2: node update MLP. One warp per node.
//   x (128) = [node(64), agg/deg (64)] -> 4 register chunks of 32.
// ---------------------------------------------------------------------------
__global__ __launch_bounds__(256)
void node_kernel(const float* __restrict__ nf,
                 const float* __restrict__ u1, const float* __restrict__ ub1,
                 const float* __restrict__ u2, const float* __restrict__ ub2,
                 float* __restrict__ out) {
    extern __shared__ float sh[];
    float* sW1 = sh;            // 128*64 = 8192
    float* sB1 = sh + 8192;     // 64
    float* sW2 = sh + 8256;     // 64*64 = 4096
    float* sB2 = sh + 12352;    // 64 -> total 12416 floats

    for (int i = threadIdx.x; i < 8192; i += blockDim.x) sW1[i] = u1[i];
    for (int i = threadIdx.x; i < 4096; i += blockDim.x) sW2[i] = u2[i];
    if (threadIdx.x < 64) sB1[threadIdx.x] = ub1[threadIdx.x];
    else if (threadIdx.x < 128) sB2[threadIdx.x - 64] = ub2[threadIdx.x - 64];
    __syncthreads();

    const int lane   = threadIdx.x & 31;
    const int warp   = (blockIdx.x * blockDim.x + threadIdx.x) >> 5;
    const int nwarps = (gridDim.x * blockDim.x) >> 5;

    for (int n = warp; n < N_NODES; n += nwarps) {
        float inv = 1.0f / (g_deg[n] + 1e-8f);
        float x0 = nf[n * NODE_DIM + lane];
        float x1 = nf[n * NODE_DIM + 32 + lane];
        float x2 = g_agg[n * HIDDEN + lane] * inv;
        float x3 = g_agg[n * HIDDEN + 32 + lane] * inv;

        float h0 = sB1[lane], h1 = sB1[32 + lane];
        #pragma unroll
        for (int c = 0; c < 4; c++) {
            #pragma unroll 8
            for (int kk = 0; kk < 32; kk++) {
                int k = c * 32 + kk;
                float xi = (c == 0) ? x0 : ((c == 1) ? x1 : ((c == 2) ? x2 : x3));
                float xk = __shfl_sync(0xFFFFFFFFu, xi, kk);
                h0 = fmaf(xk, sW1[k * 64 + lane], h0);
                h1 = fmaf(xk, sW1[k * 64 + 32 + lane], h1);
            }
        }
        h0 = fmaxf(h0, 0.0f); h1 = fmaxf(h1, 0.0f);

        float o0 = sB2[lane], o1 = sB2[32 + lane];
        #pragma unroll
        for (int c = 0; c < 2; c++) {
            #pragma unroll 8
            for (int jj = 0; jj < 32; jj++) {
                int j = c * 32 + jj;
                float hi = (c == 0) ? h0 : h1;
                float hj = __shfl_sync(0xFFFFFFFFu, hi, jj);
                o0 = fmaf(hj, sW2[j * 64 + lane], o0);
                o1 = fmaf(hj, sW2[j * 64 + 32 + lane], o1);
            }
        }
        out[n * NODE_DIM + lane] = o0;
        out[n * NODE_DIM + 32 + lane] = o1;
    }
}

// ---------------------------------------------------------------------------
extern "C" void kernel_launch(void* const* d_in, const int* in_sizes, int n_in,
                              void* d_out, int out_size) {
    const float* nf  = (const float*)d_in[0];   // node_features [50000,64]
    const float* ef  = (const float*)d_in[1];   // edge_features [800000,32]
    const float* mw1 = (const float*)d_in[2];   // msg_w1 [2,96,64]
    const float* mb1 = (const float*)d_in[3];   // msg_b1 [2,64]
    const float* mw2 = (const float*)d_in[4];   // msg_w2 [2,64,64]
    const float* mb2 = (const float*)d_in[5];   // msg_b2 [2,64]
    const float* uw1 = (const float*)d_in[6];   // upd_w1 [128,64]
    const float* ub1 = (const float*)d_in[7];   // upd_b1 [64]
    const float* uw2 = (const float*)d_in[8];   // upd_w2 [64,64]
    const float* ub2 = (const float*)d_in[9];   // upd_b2 [64]
    const int*   src = (const int*)d_in[10];    // [800000]
    const int*   dst = (const int*)d_in[11];    // [800000]
    float* out = (float*)d_out;                 // [50000,64]

    static_assert(sizeof(float) == 4, "");
    const int EDGE_SMEM = 20736 * 4;  // 82944 B
    const int NODE_SMEM = 12416 * 4;  // 49664 B
    cudaFuncSetAttribute(edge_kernel, cudaFuncAttributeMaxDynamicSharedMemorySize, EDGE_SMEM);
    cudaFuncSetAttribute(node_kernel, cudaFuncAttributeMaxDynamicSharedMemorySize, NODE_SMEM);

    zero_kernel<<<256, 256>>>();
    edge_kernel<<<296, 256, EDGE_SMEM>>>(nf, ef, mw1, mb1, mw2, mb2, src, dst);
    node_kernel<<<296, 256, NODE_SMEM>>>(nf, uw1, ub1, uw2, ub2, out);
}